// round 8
// baseline (speedup 1.0000x reference)
#include <cuda_runtime.h>
#include <cuda_bf16.h>
#include <math.h>

// Problem constants
#define S_   2048
#define D_   1024
#define NH_  8
#define NKV_ 2
#define HD_  128
#define WS_  64
#define E_   16
#define HDIM_ 512

// ---------------- scratch (device globals; no allocation allowed) ----------------
__device__ float g_h1[S_ * D_];
__device__ float g_q[S_ * D_];
__device__ float g_k[S_ * NKV_ * HD_];
__device__ float g_v[S_ * NKV_ * HD_];
__device__ float g_attn[S_ * D_];
__device__ float g_x1[S_ * D_];
__device__ float g_h2[S_ * D_];
__device__ float g_hmid[E_ * S_ * HDIM_];
__device__ float g_contrib[S_ * 2 * D_];
__device__ float g_gate[S_ * 2];
__device__ int   g_list[E_ * S_];
__device__ int   g_cnt[E_];
__device__ float g_colsum[E_];

// ---------------- utility kernels ----------------
__global__ void zero_kernel() {
    int t = threadIdx.x;
    if (t < E_) { g_cnt[t] = 0; g_colsum[t] = 0.f; }
}

__device__ __forceinline__ void rms_row(const float* __restrict__ x,
                                        const float* __restrict__ w,
                                        float* __restrict__ o) {
    int n = blockIdx.x;
    int tid = threadIdx.x;
    float4 xv = *(const float4*)&x[n * D_ + tid * 4];
    float s = xv.x * xv.x + xv.y * xv.y + xv.z * xv.z + xv.w * xv.w;
    #pragma unroll
    for (int off = 16; off; off >>= 1) s += __shfl_xor_sync(0xffffffffu, s, off);
    __shared__ float part[8];
    __shared__ float inv;
    int wid = tid >> 5, lane = tid & 31;
    if (lane == 0) part[wid] = s;
    __syncthreads();
    if (tid == 0) {
        float t = 0.f;
        #pragma unroll
        for (int i = 0; i < 8; i++) t += part[i];
        inv = rsqrtf(t / (float)D_ + 1e-6f);
    }
    __syncthreads();
    float4 wv = *(const float4*)&w[tid * 4];
    float4 ov;
    ov.x = xv.x * inv * wv.x; ov.y = xv.y * inv * wv.y;
    ov.z = xv.z * inv * wv.z; ov.w = xv.w * inv * wv.w;
    *(float4*)&o[n * D_ + tid * 4] = ov;
}

__global__ void __launch_bounds__(256) rmsnorm1_kernel(const float* __restrict__ x,
                                                       const float* __restrict__ w) {
    rms_row(x, w, g_h1);
}
__global__ void __launch_bounds__(256) rmsnorm2_kernel(const float* __restrict__ w) {
    rms_row(g_x1, w, g_h2);
}

// ================= TF32x3 tensor-core GEMM core (pre-split operands) ==============
// Block tile 128x64x16, 128 threads = 4 warps (2x2), warp tile 64x32.
// Operands stored in smem as interleaved (hi,lo) tf32 pairs (float2).
// Strides in float2 units; ASTR2,BSTR2 == 4 (mod 16) -> conflict-free LDS.64.
#define BM 128
#define BN 64
#define BK 16
#define ASTR2 132
#define BSTR2 68
#define GSMEM ((2 * BK * ASTR2 + 2 * BK * BSTR2) * 8)   // 51200 bytes

__device__ __forceinline__ unsigned f2tf(float x) {
    unsigned u; asm("cvt.rna.tf32.f32 %0, %1;" : "=r"(u) : "f"(x)); return u;
}
__device__ __forceinline__ float2 tfsplit(float x) {
    unsigned h = f2tf(x);
    float hf = __uint_as_float(h);
    unsigned l = f2tf(x - hf);
    return make_float2(hf, __uint_as_float(l));
}
__device__ __forceinline__ void mma8(float* d, const unsigned* a, const unsigned* b) {
    asm volatile(
        "mma.sync.aligned.m16n8k8.row.col.f32.tf32.tf32.f32 "
        "{%0,%1,%2,%3}, {%4,%5,%6,%7}, {%8,%9}, {%0,%1,%2,%3};\n"
        : "+f"(d[0]), "+f"(d[1]), "+f"(d[2]), "+f"(d[3])
        : "r"(a[0]), "r"(a[1]), "r"(a[2]), "r"(a[3]), "r"(b[0]), "r"(b[1]));
}

__device__ __forceinline__ void mma_gemm(const float* __restrict__ aRow,
                                         const float* __restrict__ bPtr,
                                         int ldb, int Kdim,
                                         float (&acc)[4][4][4]) {
    extern __shared__ unsigned char dynraw[];
    float2* As0 = (float2*)dynraw;
    float2* As1 = As0 + BK * ASTR2;
    float2* Bs0 = As1 + BK * ASTR2;
    float2* Bs1 = Bs0 + BK * BSTR2;
    int tid = threadIdx.x;
    int lane = tid & 31;
    int wid = tid >> 5;
    int warpM = (wid >> 1) * 64;
    int warpN = (wid & 1) * 32;
    int grp = lane >> 2, qid = lane & 3;
    int bcol = (tid & 15) * 4;
    int bk0 = tid >> 4;                 // 0..7

    #pragma unroll
    for (int m = 0; m < 4; m++)
        #pragma unroll
        for (int n = 0; n < 4; n++)
            #pragma unroll
            for (int r = 0; r < 4; r++) acc[m][n][r] = 0.f;

    float4 ar[4]; float4 br[2];
    #pragma unroll
    for (int i = 0; i < 4; i++) ar[i] = *(const float4*)(aRow + i * 4);
    br[0] = *(const float4*)(bPtr + (size_t)bk0 * ldb + bcol);
    br[1] = *(const float4*)(bPtr + (size_t)(bk0 + 8) * ldb + bcol);
    {
        #pragma unroll
        for (int i = 0; i < 4; i++) {
            As0[(i * 4 + 0) * ASTR2 + tid] = tfsplit(ar[i].x);
            As0[(i * 4 + 1) * ASTR2 + tid] = tfsplit(ar[i].y);
            As0[(i * 4 + 2) * ASTR2 + tid] = tfsplit(ar[i].z);
            As0[(i * 4 + 3) * ASTR2 + tid] = tfsplit(ar[i].w);
        }
        Bs0[bk0 * BSTR2 + bcol + 0] = tfsplit(br[0].x);
        Bs0[bk0 * BSTR2 + bcol + 1] = tfsplit(br[0].y);
        Bs0[bk0 * BSTR2 + bcol + 2] = tfsplit(br[0].z);
        Bs0[bk0 * BSTR2 + bcol + 3] = tfsplit(br[0].w);
        Bs0[(bk0 + 8) * BSTR2 + bcol + 0] = tfsplit(br[1].x);
        Bs0[(bk0 + 8) * BSTR2 + bcol + 1] = tfsplit(br[1].y);
        Bs0[(bk0 + 8) * BSTR2 + bcol + 2] = tfsplit(br[1].z);
        Bs0[(bk0 + 8) * BSTR2 + bcol + 3] = tfsplit(br[1].w);
    }
    __syncthreads();

    int T = Kdim / BK;
    for (int t = 0; t < T; ++t) {
        const float2* as = (t & 1) ? As1 : As0;
        const float2* bs = (t & 1) ? Bs1 : Bs0;
        if (t + 1 < T) {
            int k0 = (t + 1) * BK;
            #pragma unroll
            for (int i = 0; i < 4; i++) ar[i] = *(const float4*)(aRow + k0 + i * 4);
            br[0] = *(const float4*)(bPtr + (size_t)(k0 + bk0) * ldb + bcol);
            br[1] = *(const float4*)(bPtr + (size_t)(k0 + bk0 + 8) * ldb + bcol);
        }
        #pragma unroll
        for (int s = 0; s < 2; s++) {
            int ks = s * 8;
            float2 afr[4][4];
            #pragma unroll
            for (int mf = 0; mf < 4; mf++) {
                int rb = warpM + mf * 16 + grp;
                afr[mf][0] = as[(ks + qid) * ASTR2 + rb];
                afr[mf][1] = as[(ks + qid) * ASTR2 + rb + 8];
                afr[mf][2] = as[(ks + qid + 4) * ASTR2 + rb];
                afr[mf][3] = as[(ks + qid + 4) * ASTR2 + rb + 8];
            }
            #pragma unroll
            for (int nf = 0; nf < 4; nf++) {
                int nb = warpN + nf * 8 + grp;
                float2 b0 = bs[(ks + qid) * BSTR2 + nb];
                float2 b1 = bs[(ks + qid + 4) * BSTR2 + nb];
                unsigned bh[2] = {__float_as_uint(b0.x), __float_as_uint(b1.x)};
                unsigned bl[2] = {__float_as_uint(b0.y), __float_as_uint(b1.y)};
                #pragma unroll
                for (int mf = 0; mf < 4; mf++) {
                    unsigned ah[4] = {__float_as_uint(afr[mf][0].x), __float_as_uint(afr[mf][1].x),
                                      __float_as_uint(afr[mf][2].x), __float_as_uint(afr[mf][3].x)};
                    unsigned al[4] = {__float_as_uint(afr[mf][0].y), __float_as_uint(afr[mf][1].y),
                                      __float_as_uint(afr[mf][2].y), __float_as_uint(afr[mf][3].y)};
                    mma8(acc[mf][nf], al, bh);
                    mma8(acc[mf][nf], ah, bl);
                    mma8(acc[mf][nf], ah, bh);
                }
            }
        }
        if (t + 1 < T) {
            float2* asw = (t & 1) ? As0 : As1;
            float2* bsw = (t & 1) ? Bs0 : Bs1;
            #pragma unroll
            for (int i = 0; i < 4; i++) {
                asw[(i * 4 + 0) * ASTR2 + tid] = tfsplit(ar[i].x);
                asw[(i * 4 + 1) * ASTR2 + tid] = tfsplit(ar[i].y);
                asw[(i * 4 + 2) * ASTR2 + tid] = tfsplit(ar[i].z);
                asw[(i * 4 + 3) * ASTR2 + tid] = tfsplit(ar[i].w);
            }
            bsw[bk0 * BSTR2 + bcol + 0] = tfsplit(br[0].x);
            bsw[bk0 * BSTR2 + bcol + 1] = tfsplit(br[0].y);
            bsw[bk0 * BSTR2 + bcol + 2] = tfsplit(br[0].z);
            bsw[bk0 * BSTR2 + bcol + 3] = tfsplit(br[0].w);
            bsw[(bk0 + 8) * BSTR2 + bcol + 0] = tfsplit(br[1].x);
            bsw[(bk0 + 8) * BSTR2 + bcol + 1] = tfsplit(br[1].y);
            bsw[(bk0 + 8) * BSTR2 + bcol + 2] = tfsplit(br[1].z);
            bsw[(bk0 + 8) * BSTR2 + bcol + 3] = tfsplit(br[1].w);
        }
        __syncthreads();
    }
}

// ---------------- fused QKV GEMM: y tiles 0-15 Q, 16-19 K, 20-23 V ----------------
__global__ void __launch_bounds__(128) qkv_kernel(const float* __restrict__ wq, const float* __restrict__ bq,
                                                  const float* __restrict__ wk, const float* __restrict__ bk,
                                                  const float* __restrict__ wv, const float* __restrict__ bv) {
    int bm = blockIdx.x * BM;
    int tn = blockIdx.y;
    const float *B, *bias; float* C; int ldb, ldc, bn;
    if (tn < 16)      { B = wq; bias = bq; C = g_q; ldb = 1024; ldc = 1024; bn = tn * 64; }
    else if (tn < 20) { B = wk; bias = bk; C = g_k; ldb = 256;  ldc = 256;  bn = (tn - 16) * 64; }
    else              { B = wv; bias = bv; C = g_v; ldb = 256;  ldc = 256;  bn = (tn - 20) * 64; }
    float acc[4][4][4];
    const float* aRow = g_h1 + (size_t)(bm + threadIdx.x) * D_;
    mma_gemm(aRow, B + bn, ldb, D_, acc);
    int lane = threadIdx.x & 31, wid = threadIdx.x >> 5;
    int warpM = (wid >> 1) * 64, warpN = (wid & 1) * 32;
    int grp = lane >> 2, qid = lane & 3;
    #pragma unroll
    for (int mf = 0; mf < 4; mf++) {
        int r0 = bm + warpM + mf * 16 + grp;
        #pragma unroll
        for (int nf = 0; nf < 4; nf++) {
            int c0 = bn + warpN + nf * 8 + qid * 2;
            C[(size_t)r0 * ldc + c0]           = acc[mf][nf][0] + bias[c0];
            C[(size_t)r0 * ldc + c0 + 1]       = acc[mf][nf][1] + bias[c0 + 1];
            C[(size_t)(r0 + 8) * ldc + c0]     = acc[mf][nf][2] + bias[c0];
            C[(size_t)(r0 + 8) * ldc + c0 + 1] = acc[mf][nf][3] + bias[c0 + 1];
        }
    }
}

// ---------------- attention: smem-tiled, block = 32 queries x 1 kv-head ----------------
// smem: K[95][129] floats (lane-per-key column reads conflict-free),
//       V[95][132] (float4 row reads), P[8][64] per-warp prob vectors.
#define KROWS 95
#define KSTR  129
#define VSTR  132
#define VS_OFF 12256          // floats (16B aligned)
#define PS_OFF 24796          // floats
#define ATTN_SMEM ((PS_OFF + 8 * 64) * 4)   // 101,280 bytes

__global__ void __launch_bounds__(256) attn_kernel(const float* __restrict__ sinkp) {
    extern __shared__ unsigned char dynraw[];
    float* Ks = (float*)dynraw;
    float* Vs = Ks + VS_OFF;
    float* Ps = Ks + PS_OFF;
    int q0 = blockIdx.x * 32;
    int kh = blockIdx.y;
    int tid = threadIdx.x;
    int g = q0 - (WS_ - 1);           // key index of smem row 0 (may be <0)

    for (int idx = tid; idx < KROWS * 32; idx += 256) {
        int r = idx >> 5, c4 = (idx & 31) << 2;
        int key = g + r;
        float4 kv = make_float4(0.f, 0.f, 0.f, 0.f);
        float4 vv = kv;
        if (key >= 0) {
            kv = *(const float4*)&g_k[(size_t)key * (NKV_ * HD_) + kh * HD_ + c4];
            vv = *(const float4*)&g_v[(size_t)key * (NKV_ * HD_) + kh * HD_ + c4];
        }
        Ks[r * KSTR + c4 + 0] = kv.x;
        Ks[r * KSTR + c4 + 1] = kv.y;
        Ks[r * KSTR + c4 + 2] = kv.z;
        Ks[r * KSTR + c4 + 3] = kv.w;
        *(float4*)&Vs[r * VSTR + c4] = vv;
    }
    __syncthreads();

    int warp = tid >> 5, lane = tid & 31;
    float sink = *sinkp;
    const float scale = 0.08838834764831845f;  // 1/sqrt(128)

    for (int t = warp; t < 128; t += 8) {
        int qi = t & 31, hh = t >> 5;
        int i = q0 + qi, h = kh * 4 + hh;
        int jstart = i - (WS_ - 1); if (jstart < 0) jstart = 0;
        int nj = i - jstart + 1;
        bool va = lane < nj;
        bool vb = lane + 32 < nj;
        int ra = jstart + lane - g;            // always in [0, 94]
        int rb_ = vb ? (ra + 32) : ra;         // clamp invalid to a safe row
        const float* qptr = &g_q[(size_t)i * D_ + h * HD_];
        float sa = 0.f, sb = 0.f;
        #pragma unroll 8
        for (int d4 = 0; d4 < HD_; d4 += 4) {
            float4 q4 = *(const float4*)(qptr + d4);
            const float* ka = &Ks[ra * KSTR + d4];
            const float* kb = &Ks[rb_ * KSTR + d4];
            sa += q4.x * ka[0] + q4.y * ka[1] + q4.z * ka[2] + q4.w * ka[3];
            sb += q4.x * kb[0] + q4.y * kb[1] + q4.z * kb[2] + q4.w * kb[3];
        }
        sa = va ? sa * scale : -1e30f;
        sb = vb ? sb * scale : -1e30f;
        float m = fmaxf(sa, sb);
        #pragma unroll
        for (int off = 16; off; off >>= 1) m = fmaxf(m, __shfl_xor_sync(0xffffffffu, m, off));
        m = fmaxf(m, sink);
        float ea = va ? expf(sa - m) : 0.f;
        float eb = vb ? expf(sb - m) : 0.f;
        float ds = ea + eb;
        #pragma unroll
        for (int off = 16; off; off >>= 1) ds += __shfl_xor_sync(0xffffffffu, ds, off);
        ds += expf(sink - m);
        float inv = 1.0f / ds;
        Ps[warp * 64 + lane]      = ea * inv;
        Ps[warp * 64 + lane + 32] = eb * inv;
        __syncwarp();
        int d0 = lane * 4;
        float4 acc = make_float4(0.f, 0.f, 0.f, 0.f);
        for (int j = 0; j < nj; j++) {
            float p = Ps[warp * 64 + j];
            int rr = jstart + j - g;
            float4 v4 = *(const float4*)&Vs[rr * VSTR + d0];
            acc.x += p * v4.x; acc.y += p * v4.y; acc.z += p * v4.z; acc.w += p * v4.w;
        }
        *(float4*)&g_attn[(size_t)i * D_ + h * HD_ + d0] = acc;
        __syncwarp();
    }
}

// ---------------- output projection + residual ----------------
__global__ void __launch_bounds__(128) wo_kernel(const float* __restrict__ woW, const float* __restrict__ bo,
                                                 const float* __restrict__ x) {
    int bm = blockIdx.x * BM;
    int bn = blockIdx.y * BN;
    float acc[4][4][4];
    const float* aRow = g_attn + (size_t)(bm + threadIdx.x) * D_;
    mma_gemm(aRow, woW + bn, D_, D_, acc);
    int lane = threadIdx.x & 31, wid = threadIdx.x >> 5;
    int warpM = (wid >> 1) * 64, warpN = (wid & 1) * 32;
    int grp = lane >> 2, qid = lane & 3;
    #pragma unroll
    for (int mf = 0; mf < 4; mf++) {
        int r0 = bm + warpM + mf * 16 + grp;
        #pragma unroll
        for (int nf = 0; nf < 4; nf++) {
            int c0 = bn + warpN + nf * 8 + qid * 2;
            g_x1[(size_t)r0 * D_ + c0]           = acc[mf][nf][0] + bo[c0]     + x[(size_t)r0 * D_ + c0];
            g_x1[(size_t)r0 * D_ + c0 + 1]       = acc[mf][nf][1] + bo[c0 + 1] + x[(size_t)r0 * D_ + c0 + 1];
            g_x1[(size_t)(r0 + 8) * D_ + c0]     = acc[mf][nf][2] + bo[c0]     + x[(size_t)(r0 + 8) * D_ + c0];
            g_x1[(size_t)(r0 + 8) * D_ + c0 + 1] = acc[mf][nf][3] + bo[c0 + 1] + x[(size_t)(r0 + 8) * D_ + c0 + 1];
        }
    }
}

// ---------------- router ----------------
__global__ void __launch_bounds__(128) router_kernel(const float* __restrict__ rw,
                                                     const float* __restrict__ rb) {
    int n = blockIdx.x;
    int tid = threadIdx.x;
    float acc[16];
    #pragma unroll
    for (int e = 0; e < 16; e++) acc[e] = 0.f;
    for (int d = tid; d < D_; d += 128) {
        float hv = g_h2[(size_t)n * D_ + d];
        const float4* r4 = (const float4*)(rw + (size_t)d * E_);
        float4 r0 = r4[0], r1 = r4[1], r2 = r4[2], r3 = r4[3];
        acc[0]  += hv * r0.x; acc[1]  += hv * r0.y; acc[2]  += hv * r0.z; acc[3]  += hv * r0.w;
        acc[4]  += hv * r1.x; acc[5]  += hv * r1.y; acc[6]  += hv * r1.z; acc[7]  += hv * r1.w;
        acc[8]  += hv * r2.x; acc[9]  += hv * r2.y; acc[10] += hv * r2.z; acc[11] += hv * r2.w;
        acc[12] += hv * r3.x; acc[13] += hv * r3.y; acc[14] += hv * r3.z; acc[15] += hv * r3.w;
    }
    #pragma unroll
    for (int e = 0; e < 16; e++) {
        #pragma unroll
        for (int off = 16; off; off >>= 1) acc[e] += __shfl_xor_sync(0xffffffffu, acc[e], off);
    }
    __shared__ float part[4][16];
    __shared__ float slog[16];
    int wid = tid >> 5, lane = tid & 31;
    if (lane == 0) {
        #pragma unroll
        for (int e = 0; e < 16; e++) part[wid][e] = acc[e];
    }
    __syncthreads();
    if (tid < 16) {
        float s = part[0][tid] + part[1][tid] + part[2][tid] + part[3][tid];
        slog[tid] = (s + rb[tid]) / 0.1f;
    }
    __syncthreads();
    if (tid == 0) {
        float l[16];
        float m = -1e30f;
        #pragma unroll
        for (int e = 0; e < 16; e++) { l[e] = slog[e]; m = fmaxf(m, l[e]); }
        float sum = 0.f;
        #pragma unroll
        for (int e = 0; e < 16; e++) sum += expf(l[e] - m);
        float invs = 1.0f / sum;
        #pragma unroll
        for (int e = 0; e < 16; e++) atomicAdd(&g_colsum[e], expf(l[e] - m) * invs);
        int i1 = 0;
        #pragma unroll
        for (int e = 1; e < 16; e++) if (l[e] > l[i1]) i1 = e;
        int i2 = (i1 == 0) ? 1 : 0;
        #pragma unroll
        for (int e = 0; e < 16; e++) if (e != i1 && l[e] > l[i2]) i2 = e;
        float e2 = expf(l[i2] - l[i1]);
        g_gate[n * 2 + 0] = 1.0f / (1.0f + e2);
        g_gate[n * 2 + 1] = e2 / (1.0f + e2);
        int p0 = atomicAdd(&g_cnt[i1], 1); g_list[i1 * S_ + p0] = n * 2 + 0;
        int p1 = atomicAdd(&g_cnt[i2], 1); g_list[i2 * S_ + p1] = n * 2 + 1;
    }
}

__global__ void aux_kernel(float* __restrict__ outp) {
    float v = (threadIdx.x < 16) ? g_colsum[threadIdx.x] : 0.f;
    v = v * v;
    #pragma unroll
    for (int off = 16; off; off >>= 1) v += __shfl_xor_sync(0xffffffffu, v, off);
    if (threadIdx.x == 0) outp[0] = v * (1.0f / (float)E_) * 1e-5f;
}

// ---------------- MoE GEMM 1: hmid = silu(X_gather @ w1[e] + b1[e]) ----------------
__global__ void __launch_bounds__(128) moe1_kernel(const float* __restrict__ w1,
                                                   const float* __restrict__ b1) {
    int e = blockIdx.z;
    int cnt = g_cnt[e];
    int bm = blockIdx.x * BM;
    if (bm >= cnt) return;
    int bn = blockIdx.y * BN;
    int ar = bm + threadIdx.x;
    if (ar >= cnt) ar = cnt - 1;
    int pair = g_list[e * S_ + ar];
    const float* aRow = g_h2 + (size_t)(pair >> 1) * D_;
    float acc[4][4][4];
    mma_gemm(aRow, w1 + (size_t)e * D_ * HDIM_ + bn, HDIM_, D_, acc);
    int lane = threadIdx.x & 31, wid = threadIdx.x >> 5;
    int warpM = (wid >> 1) * 64, warpN = (wid & 1) * 32;
    int grp = lane >> 2, qid = lane & 3;
    #pragma unroll
    for (int mf = 0; mf < 4; mf++) {
        int r0 = bm + warpM + mf * 16 + grp;
        #pragma unroll
        for (int nf = 0; nf < 4; nf++) {
            int c0 = bn + warpN + nf * 8 + qid * 2;
            #pragma unroll
            for (int rr = 0; rr < 2; rr++) {
                int r = r0 + rr * 8;
                if (r < cnt) {
                    float t0 = acc[mf][nf][rr * 2 + 0] + b1[e * HDIM_ + c0];
                    float t1 = acc[mf][nf][rr * 2 + 1] + b1[e * HDIM_ + c0 + 1];
                    g_hmid[(size_t)(e * S_ + r) * HDIM_ + c0]     = t0 / (1.0f + expf(-t0));
                    g_hmid[(size_t)(e * S_ + r) * HDIM_ + c0 + 1] = t1 / (1.0f + expf(-t1));
                }
            }
        }
    }
}

// ---------------- MoE GEMM 2: contrib[pair] = gate * (hmid @ w2[e] + b2[e]) ----------------
__global__ void __launch_bounds__(128) moe2_kernel(const float* __restrict__ w2,
                                                   const float* __restrict__ b2) {
    int e = blockIdx.z;
    int cnt = g_cnt[e];
    int bm = blockIdx.x * BM;
    if (bm >= cnt) return;
    int bn = blockIdx.y * BN;
    int ar = bm + threadIdx.x;
    if (ar >= cnt) ar = cnt - 1;
    const float* aRow = g_hmid + (size_t)(e * S_ + ar) * HDIM_;
    float acc[4][4][4];
    mma_gemm(aRow, w2 + (size_t)e * HDIM_ * D_ + bn, D_, HDIM_, acc);
    int lane = threadIdx.x & 31, wid = threadIdx.x >> 5;
    int warpM = (wid >> 1) * 64, warpN = (wid & 1) * 32;
    int grp = lane >> 2, qid = lane & 3;
    #pragma unroll
    for (int mf = 0; mf < 4; mf++) {
        int r0 = bm + warpM + mf * 16 + grp;
        #pragma unroll
        for (int nf = 0; nf < 4; nf++) {
            int c0 = bn + warpN + nf * 8 + qid * 2;
            #pragma unroll
            for (int rr = 0; rr < 2; rr++) {
                int r = r0 + rr * 8;
                if (r < cnt) {
                    int pair = g_list[e * S_ + r];
                    float g = g_gate[pair];
                    g_contrib[(size_t)pair * D_ + c0]     = g * (acc[mf][nf][rr * 2 + 0] + b2[e * D_ + c0]);
                    g_contrib[(size_t)pair * D_ + c0 + 1] = g * (acc[mf][nf][rr * 2 + 1] + b2[e * D_ + c0 + 1]);
                }
            }
        }
    }
}

// ---------------- final combine ----------------
__global__ void __launch_bounds__(256) combine_kernel(float* __restrict__ out) {
    int n = blockIdx.x;
    int d = threadIdx.x * 4;
    float4 a = *(const float4*)&g_x1[(size_t)n * D_ + d];
    float4 b = *(const float4*)&g_contrib[(size_t)(n * 2 + 0) * D_ + d];
    float4 c = *(const float4*)&g_contrib[(size_t)(n * 2 + 1) * D_ + d];
    float4 r;
    r.x = a.x + b.x + c.x; r.y = a.y + b.y + c.y;
    r.z = a.z + b.z + c.z; r.w = a.w + b.w + c.w;
    *(float4*)&out[(size_t)n * D_ + d] = r;
}

// ---------------- host launcher ----------------
extern "C" void kernel_launch(void* const* d_in, const int* in_sizes, int n_in,
                              void* d_out, int out_size) {
    const float* x    = (const float*)d_in[0];
    const float* n1w  = (const float*)d_in[1];
    const float* wq   = (const float*)d_in[2];
    const float* bq   = (const float*)d_in[3];
    const float* wk   = (const float*)d_in[4];
    const float* bk   = (const float*)d_in[5];
    const float* wv   = (const float*)d_in[6];
    const float* bv   = (const float*)d_in[7];
    const float* woW  = (const float*)d_in[8];
    const float* bo   = (const float*)d_in[9];
    const float* sink = (const float*)d_in[10];
    const float* n2w  = (const float*)d_in[11];
    const float* rw   = (const float*)d_in[12];
    const float* rb   = (const float*)d_in[13];
    const float* w1   = (const float*)d_in[14];
    const float* b1   = (const float*)d_in[15];
    const float* w2   = (const float*)d_in[16];
    const float* b2   = (const float*)d_in[17];
    float* out = (float*)d_out;

    // raise dynamic smem limits (idempotent, non-stream API)
    cudaFuncSetAttribute(qkv_kernel,  cudaFuncAttributeMaxDynamicSharedMemorySize, GSMEM);
    cudaFuncSetAttribute(wo_kernel,   cudaFuncAttributeMaxDynamicSharedMemorySize, GSMEM);
    cudaFuncSetAttribute(moe1_kernel, cudaFuncAttributeMaxDynamicSharedMemorySize, GSMEM);
    cudaFuncSetAttribute(moe2_kernel, cudaFuncAttributeMaxDynamicSharedMemorySize, GSMEM);
    cudaFuncSetAttribute(attn_kernel, cudaFuncAttributeMaxDynamicSharedMemorySize, ATTN_SMEM);

    zero_kernel<<<1, 32>>>();
    rmsnorm1_kernel<<<S_, 256>>>(x, n1w);
    qkv_kernel<<<dim3(S_ / BM, 24), 128, GSMEM>>>(wq, bq, wk, bk, wv, bv);
    attn_kernel<<<dim3(S_ / 32, NKV_), 256, ATTN_SMEM>>>(sink);
    wo_kernel<<<dim3(S_ / BM, D_ / BN), 128, GSMEM>>>(woW, bo, x);
    rmsnorm2_kernel<<<S_, 256>>>(n2w);
    router_kernel<<<S_, 128>>>(rw, rb);
    if (out_size > S_ * D_) {
        aux_kernel<<<1, 32>>>(out + (size_t)S_ * D_);
    }
    moe1_kernel<<<dim3(S_ / BM, HDIM_ / BN, E_), 128, GSMEM>>>(w1, b1);
    moe2_kernel<<<dim3(S_ / BM, D_ / BN, E_), 128, GSMEM>>>(w2, b2);
    combine_kernel<<<S_, 256>>>(out);
}

// round 9
// speedup vs baseline: 1.4700x; 1.4700x over previous
#include <cuda_runtime.h>
#include <cuda_bf16.h>
#include <math.h>

// Problem constants
#define S_   2048
#define D_   1024
#define NH_  8
#define NKV_ 2
#define HD_  128
#define WS_  64
#define E_   16
#define HDIM_ 512

// ---------------- scratch (device globals; no allocation allowed) ----------------
__device__ float g_h1[S_ * D_];
__device__ float g_q[S_ * D_];
__device__ float g_k[S_ * NKV_ * HD_];
__device__ float g_v[S_ * NKV_ * HD_];
__device__ float g_attn[S_ * D_];
__device__ float g_x1[S_ * D_];
__device__ float g_h2[S_ * D_];
__device__ float g_hmid[E_ * S_ * HDIM_];
__device__ float g_contrib[S_ * 2 * D_];
__device__ float g_gate[S_ * 2];
__device__ int   g_list[E_ * S_];
__device__ int   g_cnt[E_];
__device__ float g_colsum[E_];

// ---------------- utility kernels ----------------
__global__ void zero_kernel() {
    int t = threadIdx.x;
    if (t < E_) { g_cnt[t] = 0; g_colsum[t] = 0.f; }
}

__device__ __forceinline__ void rms_row(const float* __restrict__ x,
                                        const float* __restrict__ w,
                                        float* __restrict__ o) {
    int n = blockIdx.x;
    int tid = threadIdx.x;
    float4 xv = *(const float4*)&x[n * D_ + tid * 4];
    float s = xv.x * xv.x + xv.y * xv.y + xv.z * xv.z + xv.w * xv.w;
    #pragma unroll
    for (int off = 16; off; off >>= 1) s += __shfl_xor_sync(0xffffffffu, s, off);
    __shared__ float part[8];
    __shared__ float inv;
    int wid = tid >> 5, lane = tid & 31;
    if (lane == 0) part[wid] = s;
    __syncthreads();
    if (tid == 0) {
        float t = 0.f;
        #pragma unroll
        for (int i = 0; i < 8; i++) t += part[i];
        inv = rsqrtf(t / (float)D_ + 1e-6f);
    }
    __syncthreads();
    float4 wv = *(const float4*)&w[tid * 4];
    float4 ov;
    ov.x = xv.x * inv * wv.x; ov.y = xv.y * inv * wv.y;
    ov.z = xv.z * inv * wv.z; ov.w = xv.w * inv * wv.w;
    *(float4*)&o[n * D_ + tid * 4] = ov;
}

__global__ void __launch_bounds__(256) rmsnorm1_kernel(const float* __restrict__ x,
                                                       const float* __restrict__ w) {
    rms_row(x, w, g_h1);
}
__global__ void __launch_bounds__(256) rmsnorm2_kernel(const float* __restrict__ w) {
    rms_row(g_x1, w, g_h2);
}

// ================= bf16x3 tensor-core GEMM core =================
// Block tile 128x64x16, 128 threads = 4 warps (2x2), warp tile 64x32.
// A,B split into (hi,lo) bf16 at staging; smem holds bf16x2 k-pairs:
//   A: [kpair(8)][row(128)] stride 136 (==8 mod 32 -> conflict-free frag LDS)
//   B: [kpair(8)][col(64)]  stride 72
// 3 mma.m16n8k16 per (mf,nf) per K-tile: al*bh + ah*bl + ah*bh.
#define BM 128
#define BN 64
#define BK 16
#define KP 8
#define AS 136
#define BS 72

__device__ __forceinline__ void bfsplit2(float x0, float x1, unsigned& hi, unsigned& lo) {
    __nv_bfloat162 h = __float22bfloat162_rn(make_float2(x0, x1));
    float h0 = __low2float(h);
    float h1 = __high2float(h);
    __nv_bfloat162 l = __float22bfloat162_rn(make_float2(x0 - h0, x1 - h1));
    hi = *reinterpret_cast<unsigned*>(&h);
    lo = *reinterpret_cast<unsigned*>(&l);
}

__device__ __forceinline__ void mma16(float* d, const unsigned* a, const unsigned* b) {
    asm volatile(
        "mma.sync.aligned.m16n8k16.row.col.f32.bf16.bf16.f32 "
        "{%0,%1,%2,%3}, {%4,%5,%6,%7}, {%8,%9}, {%0,%1,%2,%3};\n"
        : "+f"(d[0]), "+f"(d[1]), "+f"(d[2]), "+f"(d[3])
        : "r"(a[0]), "r"(a[1]), "r"(a[2]), "r"(a[3]), "r"(b[0]), "r"(b[1]));
}

// aRow: this thread's A row base (row bm+tid), contiguous K.
// bPtr: B + bn (row-major, leading dim ldb over K rows).
__device__ __forceinline__ void mma_gemm(const float* __restrict__ aRow,
                                         const float* __restrict__ bPtr,
                                         int ldb, int Kdim,
                                         float (&acc)[4][4][4]) {
    __shared__ __align__(16) unsigned Ah[2][KP * AS];
    __shared__ __align__(16) unsigned Al[2][KP * AS];
    __shared__ __align__(16) unsigned Bh[2][KP * BS];
    __shared__ __align__(16) unsigned Bl[2][KP * BS];
    int tid = threadIdx.x;
    int lane = tid & 31;
    int wid = tid >> 5;
    int warpM = (wid >> 1) * 64;
    int warpN = (wid & 1) * 32;
    int grp = lane >> 2, qid = lane & 3;
    int nc = (tid & 15) * 4;            // B staging col
    int kp = tid >> 4;                  // B staging kpair 0..7

    #pragma unroll
    for (int m = 0; m < 4; m++)
        #pragma unroll
        for (int n = 0; n < 4; n++)
            #pragma unroll
            for (int r = 0; r < 4; r++) acc[m][n][r] = 0.f;

    float4 ar[4]; float4 br[2];
    // prologue: load K-tile 0, split+stage into buffer 0
    #pragma unroll
    for (int i = 0; i < 4; i++) ar[i] = *(const float4*)(aRow + i * 4);
    br[0] = *(const float4*)(bPtr + (size_t)(2 * kp) * ldb + nc);
    br[1] = *(const float4*)(bPtr + (size_t)(2 * kp + 1) * ldb + nc);
    {
        #pragma unroll
        for (int i = 0; i < 4; i++) {
            unsigned h, l;
            bfsplit2(ar[i].x, ar[i].y, h, l);
            Ah[0][(2 * i) * AS + tid] = h; Al[0][(2 * i) * AS + tid] = l;
            bfsplit2(ar[i].z, ar[i].w, h, l);
            Ah[0][(2 * i + 1) * AS + tid] = h; Al[0][(2 * i + 1) * AS + tid] = l;
        }
        uint4 hv, lv;
        bfsplit2(br[0].x, br[1].x, hv.x, lv.x);
        bfsplit2(br[0].y, br[1].y, hv.y, lv.y);
        bfsplit2(br[0].z, br[1].z, hv.z, lv.z);
        bfsplit2(br[0].w, br[1].w, hv.w, lv.w);
        *(uint4*)&Bh[0][kp * BS + nc] = hv;
        *(uint4*)&Bl[0][kp * BS + nc] = lv;
    }
    __syncthreads();

    int T = Kdim / BK;
    for (int t = 0; t < T; ++t) {
        int buf = t & 1;
        if (t + 1 < T) {   // prefetch next K-tile into registers
            int k0 = (t + 1) * BK;
            #pragma unroll
            for (int i = 0; i < 4; i++) ar[i] = *(const float4*)(aRow + k0 + i * 4);
            br[0] = *(const float4*)(bPtr + (size_t)(k0 + 2 * kp) * ldb + nc);
            br[1] = *(const float4*)(bPtr + (size_t)(k0 + 2 * kp + 1) * ldb + nc);
        }
        const unsigned* ah = Ah[buf]; const unsigned* al = Al[buf];
        const unsigned* bh = Bh[buf]; const unsigned* bl = Bl[buf];
        // A fragments for all 4 mf
        unsigned afh[4][4], afl[4][4];
        #pragma unroll
        for (int mf = 0; mf < 4; mf++) {
            int rb = warpM + mf * 16 + grp;
            afh[mf][0] = ah[qid * AS + rb];
            afh[mf][1] = ah[qid * AS + rb + 8];
            afh[mf][2] = ah[(qid + 4) * AS + rb];
            afh[mf][3] = ah[(qid + 4) * AS + rb + 8];
            afl[mf][0] = al[qid * AS + rb];
            afl[mf][1] = al[qid * AS + rb + 8];
            afl[mf][2] = al[(qid + 4) * AS + rb];
            afl[mf][3] = al[(qid + 4) * AS + rb + 8];
        }
        #pragma unroll
        for (int nf = 0; nf < 4; nf++) {
            int nb = warpN + nf * 8 + grp;
            unsigned bfh[2], bfl[2];
            bfh[0] = bh[qid * BS + nb];
            bfh[1] = bh[(qid + 4) * BS + nb];
            bfl[0] = bl[qid * BS + nb];
            bfl[1] = bl[(qid + 4) * BS + nb];
            #pragma unroll
            for (int mf = 0; mf < 4; mf++) {
                mma16(acc[mf][nf], afl[mf], bfh);
                mma16(acc[mf][nf], afh[mf], bfl);
                mma16(acc[mf][nf], afh[mf], bfh);
            }
        }
        if (t + 1 < T) {   // stage prefetched tile into other buffer
            int nb_ = buf ^ 1;
            #pragma unroll
            for (int i = 0; i < 4; i++) {
                unsigned h, l;
                bfsplit2(ar[i].x, ar[i].y, h, l);
                Ah[nb_][(2 * i) * AS + tid] = h; Al[nb_][(2 * i) * AS + tid] = l;
                bfsplit2(ar[i].z, ar[i].w, h, l);
                Ah[nb_][(2 * i + 1) * AS + tid] = h; Al[nb_][(2 * i + 1) * AS + tid] = l;
            }
            uint4 hv, lv;
            bfsplit2(br[0].x, br[1].x, hv.x, lv.x);
            bfsplit2(br[0].y, br[1].y, hv.y, lv.y);
            bfsplit2(br[0].z, br[1].z, hv.z, lv.z);
            bfsplit2(br[0].w, br[1].w, hv.w, lv.w);
            *(uint4*)&Bh[nb_][kp * BS + nc] = hv;
            *(uint4*)&Bl[nb_][kp * BS + nc] = lv;
        }
        __syncthreads();
    }
}

// ---------------- fused QKV GEMM: y tiles 0-15 Q, 16-19 K, 20-23 V ----------------
__global__ void __launch_bounds__(128) qkv_kernel(const float* __restrict__ wq, const float* __restrict__ bq,
                                                  const float* __restrict__ wk, const float* __restrict__ bk,
                                                  const float* __restrict__ wv, const float* __restrict__ bv) {
    int bm = blockIdx.x * BM;
    int tn = blockIdx.y;
    const float *B, *bias; float* C; int ldb, ldc, bn;
    if (tn < 16)      { B = wq; bias = bq; C = g_q; ldb = 1024; ldc = 1024; bn = tn * 64; }
    else if (tn < 20) { B = wk; bias = bk; C = g_k; ldb = 256;  ldc = 256;  bn = (tn - 16) * 64; }
    else              { B = wv; bias = bv; C = g_v; ldb = 256;  ldc = 256;  bn = (tn - 20) * 64; }
    float acc[4][4][4];
    const float* aRow = g_h1 + (size_t)(bm + threadIdx.x) * D_;
    mma_gemm(aRow, B + bn, ldb, D_, acc);
    int lane = threadIdx.x & 31, wid = threadIdx.x >> 5;
    int warpM = (wid >> 1) * 64, warpN = (wid & 1) * 32;
    int grp = lane >> 2, qid = lane & 3;
    #pragma unroll
    for (int mf = 0; mf < 4; mf++) {
        int r0 = bm + warpM + mf * 16 + grp;
        #pragma unroll
        for (int nf = 0; nf < 4; nf++) {
            int c0 = bn + warpN + nf * 8 + qid * 2;
            C[(size_t)r0 * ldc + c0]           = acc[mf][nf][0] + bias[c0];
            C[(size_t)r0 * ldc + c0 + 1]       = acc[mf][nf][1] + bias[c0 + 1];
            C[(size_t)(r0 + 8) * ldc + c0]     = acc[mf][nf][2] + bias[c0];
            C[(size_t)(r0 + 8) * ldc + c0 + 1] = acc[mf][nf][3] + bias[c0 + 1];
        }
    }
}

// ---------------- attention: one warp per (query, head) ----------------
__global__ void __launch_bounds__(256) attn_kernel(const float* __restrict__ sinkp) {
    int i = blockIdx.x;
    int h = threadIdx.x >> 5;
    int lane = threadIdx.x & 31;
    float sink = *sinkp;
    int kh = h >> 2;
    const float4 qv = *(const float4*)&g_q[(size_t)i * D_ + h * HD_ + lane * 4];
    int jstart = i - (WS_ - 1); if (jstart < 0) jstart = 0;
    int nj = i - jstart + 1;
    const float scale = 0.08838834764831845f;
    float s0 = -1e30f, s1 = -1e30f;
    for (int jj = 0; jj < nj; ++jj) {
        int j = jstart + jj;
        float4 kv = *(const float4*)&g_k[(size_t)j * (NKV_ * HD_) + kh * HD_ + lane * 4];
        float p = qv.x * kv.x + qv.y * kv.y + qv.z * kv.z + qv.w * kv.w;
        #pragma unroll
        for (int off = 16; off; off >>= 1) p += __shfl_xor_sync(0xffffffffu, p, off);
        p *= scale;
        if (lane == (jj & 31)) { if (jj < 32) s0 = p; else s1 = p; }
    }
    float m = fmaxf(s0, s1);
    #pragma unroll
    for (int off = 16; off; off >>= 1) m = fmaxf(m, __shfl_xor_sync(0xffffffffu, m, off));
    m = fmaxf(m, sink);
    float e0 = expf(s0 - m), e1 = expf(s1 - m);
    float dsum = e0 + e1;
    #pragma unroll
    for (int off = 16; off; off >>= 1) dsum += __shfl_xor_sync(0xffffffffu, dsum, off);
    dsum += expf(sink - m);
    float4 acc = {0.f, 0.f, 0.f, 0.f};
    for (int jj = 0; jj < nj; ++jj) {
        int j = jstart + jj;
        float esel = (jj < 32) ? e0 : e1;
        float p = __shfl_sync(0xffffffffu, esel, jj & 31);
        float4 vv = *(const float4*)&g_v[(size_t)j * (NKV_ * HD_) + kh * HD_ + lane * 4];
        acc.x += p * vv.x; acc.y += p * vv.y; acc.z += p * vv.z; acc.w += p * vv.w;
    }
    float inv = 1.0f / dsum;
    acc.x *= inv; acc.y *= inv; acc.z *= inv; acc.w *= inv;
    *(float4*)&g_attn[(size_t)i * D_ + h * HD_ + lane * 4] = acc;
}

// ---------------- output projection + residual ----------------
__global__ void __launch_bounds__(128) wo_kernel(const float* __restrict__ woW, const float* __restrict__ bo,
                                                 const float* __restrict__ x) {
    int bm = blockIdx.x * BM;
    int bn = blockIdx.y * BN;
    float acc[4][4][4];
    const float* aRow = g_attn + (size_t)(bm + threadIdx.x) * D_;
    mma_gemm(aRow, woW + bn, D_, D_, acc);
    int lane = threadIdx.x & 31, wid = threadIdx.x >> 5;
    int warpM = (wid >> 1) * 64, warpN = (wid & 1) * 32;
    int grp = lane >> 2, qid = lane & 3;
    #pragma unroll
    for (int mf = 0; mf < 4; mf++) {
        int r0 = bm + warpM + mf * 16 + grp;
        #pragma unroll
        for (int nf = 0; nf < 4; nf++) {
            int c0 = bn + warpN + nf * 8 + qid * 2;
            g_x1[(size_t)r0 * D_ + c0]           = acc[mf][nf][0] + bo[c0]     + x[(size_t)r0 * D_ + c0];
            g_x1[(size_t)r0 * D_ + c0 + 1]       = acc[mf][nf][1] + bo[c0 + 1] + x[(size_t)r0 * D_ + c0 + 1];
            g_x1[(size_t)(r0 + 8) * D_ + c0]     = acc[mf][nf][2] + bo[c0]     + x[(size_t)(r0 + 8) * D_ + c0];
            g_x1[(size_t)(r0 + 8) * D_ + c0 + 1] = acc[mf][nf][3] + bo[c0 + 1] + x[(size_t)(r0 + 8) * D_ + c0 + 1];
        }
    }
}

// ---------------- router ----------------
__global__ void __launch_bounds__(128) router_kernel(const float* __restrict__ rw,
                                                     const float* __restrict__ rb) {
    int n = blockIdx.x;
    int tid = threadIdx.x;
    float acc[16];
    #pragma unroll
    for (int e = 0; e < 16; e++) acc[e] = 0.f;
    for (int d = tid; d < D_; d += 128) {
        float hv = g_h2[(size_t)n * D_ + d];
        const float4* r4 = (const float4*)(rw + (size_t)d * E_);
        float4 r0 = r4[0], r1 = r4[1], r2 = r4[2], r3 = r4[3];
        acc[0]  += hv * r0.x; acc[1]  += hv * r0.y; acc[2]  += hv * r0.z; acc[3]  += hv * r0.w;
        acc[4]  += hv * r1.x; acc[5]  += hv * r1.y; acc[6]  += hv * r1.z; acc[7]  += hv * r1.w;
        acc[8]  += hv * r2.x; acc[9]  += hv * r2.y; acc[10] += hv * r2.z; acc[11] += hv * r2.w;
        acc[12] += hv * r3.x; acc[13] += hv * r3.y; acc[14] += hv * r3.z; acc[15] += hv * r3.w;
    }
    #pragma unroll
    for (int e = 0; e < 16; e++) {
        #pragma unroll
        for (int off = 16; off; off >>= 1) acc[e] += __shfl_xor_sync(0xffffffffu, acc[e], off);
    }
    __shared__ float part[4][16];
    __shared__ float slog[16];
    int wid = tid >> 5, lane = tid & 31;
    if (lane == 0) {
        #pragma unroll
        for (int e = 0; e < 16; e++) part[wid][e] = acc[e];
    }
    __syncthreads();
    if (tid < 16) {
        float s = part[0][tid] + part[1][tid] + part[2][tid] + part[3][tid];
        slog[tid] = (s + rb[tid]) / 0.1f;
    }
    __syncthreads();
    if (tid == 0) {
        float l[16];
        float m = -1e30f;
        #pragma unroll
        for (int e = 0; e < 16; e++) { l[e] = slog[e]; m = fmaxf(m, l[e]); }
        float sum = 0.f;
        #pragma unroll
        for (int e = 0; e < 16; e++) sum += expf(l[e] - m);
        float invs = 1.0f / sum;
        #pragma unroll
        for (int e = 0; e < 16; e++) atomicAdd(&g_colsum[e], expf(l[e] - m) * invs);
        int i1 = 0;
        #pragma unroll
        for (int e = 1; e < 16; e++) if (l[e] > l[i1]) i1 = e;
        int i2 = (i1 == 0) ? 1 : 0;
        #pragma unroll
        for (int e = 0; e < 16; e++) if (e != i1 && l[e] > l[i2]) i2 = e;
        float e2 = expf(l[i2] - l[i1]);
        g_gate[n * 2 + 0] = 1.0f / (1.0f + e2);
        g_gate[n * 2 + 1] = e2 / (1.0f + e2);
        int p0 = atomicAdd(&g_cnt[i1], 1); g_list[i1 * S_ + p0] = n * 2 + 0;
        int p1 = atomicAdd(&g_cnt[i2], 1); g_list[i2 * S_ + p1] = n * 2 + 1;
    }
}

__global__ void aux_kernel(float* __restrict__ outp) {
    float v = (threadIdx.x < 16) ? g_colsum[threadIdx.x] : 0.f;
    v = v * v;
    #pragma unroll
    for (int off = 16; off; off >>= 1) v += __shfl_xor_sync(0xffffffffu, v, off);
    if (threadIdx.x == 0) outp[0] = v * (1.0f / (float)E_) * 1e-5f;
}

// ---------------- MoE GEMM 1: hmid = silu(X_gather @ w1[e] + b1[e]) ----------------
__global__ void __launch_bounds__(128) moe1_kernel(const float* __restrict__ w1,
                                                   const float* __restrict__ b1) {
    int e = blockIdx.z;
    int cnt = g_cnt[e];
    int bm = blockIdx.x * BM;
    if (bm >= cnt) return;
    int bn = blockIdx.y * BN;
    int ar = bm + threadIdx.x;
    if (ar >= cnt) ar = cnt - 1;
    int pair = g_list[e * S_ + ar];
    const float* aRow = g_h2 + (size_t)(pair >> 1) * D_;
    float acc[4][4][4];
    mma_gemm(aRow, w1 + (size_t)e * D_ * HDIM_ + bn, HDIM_, D_, acc);
    int lane = threadIdx.x & 31, wid = threadIdx.x >> 5;
    int warpM = (wid >> 1) * 64, warpN = (wid & 1) * 32;
    int grp = lane >> 2, qid = lane & 3;
    #pragma unroll
    for (int mf = 0; mf < 4; mf++) {
        int r0 = bm + warpM + mf * 16 + grp;
        #pragma unroll
        for (int nf = 0; nf < 4; nf++) {
            int c0 = bn + warpN + nf * 8 + qid * 2;
            #pragma unroll
            for (int rr = 0; rr < 2; rr++) {
                int r = r0 + rr * 8;
                if (r < cnt) {
                    float t0 = acc[mf][nf][rr * 2 + 0] + b1[e * HDIM_ + c0];
                    float t1 = acc[mf][nf][rr * 2 + 1] + b1[e * HDIM_ + c0 + 1];
                    g_hmid[(size_t)(e * S_ + r) * HDIM_ + c0]     = t0 / (1.0f + expf(-t0));
                    g_hmid[(size_t)(e * S_ + r) * HDIM_ + c0 + 1] = t1 / (1.0f + expf(-t1));
                }
            }
        }
    }
}

// ---------------- MoE GEMM 2: contrib[pair] = gate * (hmid @ w2[e] + b2[e]) ----------------
__global__ void __launch_bounds__(128) moe2_kernel(const float* __restrict__ w2,
                                                   const float* __restrict__ b2) {
    int e = blockIdx.z;
    int cnt = g_cnt[e];
    int bm = blockIdx.x * BM;
    if (bm >= cnt) return;
    int bn = blockIdx.y * BN;
    int ar = bm + threadIdx.x;
    if (ar >= cnt) ar = cnt - 1;
    const float* aRow = g_hmid + (size_t)(e * S_ + ar) * HDIM_;
    float acc[4][4][4];
    mma_gemm(aRow, w2 + (size_t)e * HDIM_ * D_ + bn, D_, HDIM_, acc);
    int lane = threadIdx.x & 31, wid = threadIdx.x >> 5;
    int warpM = (wid >> 1) * 64, warpN = (wid & 1) * 32;
    int grp = lane >> 2, qid = lane & 3;
    #pragma unroll
    for (int mf = 0; mf < 4; mf++) {
        int r0 = bm + warpM + mf * 16 + grp;
        #pragma unroll
        for (int nf = 0; nf < 4; nf++) {
            int c0 = bn + warpN + nf * 8 + qid * 2;
            #pragma unroll
            for (int rr = 0; rr < 2; rr++) {
                int r = r0 + rr * 8;
                if (r < cnt) {
                    int pair = g_list[e * S_ + r];
                    float g = g_gate[pair];
                    g_contrib[(size_t)pair * D_ + c0]     = g * (acc[mf][nf][rr * 2 + 0] + b2[e * D_ + c0]);
                    g_contrib[(size_t)pair * D_ + c0 + 1] = g * (acc[mf][nf][rr * 2 + 1] + b2[e * D_ + c0 + 1]);
                }
            }
        }
    }
}

// ---------------- final combine ----------------
__global__ void __launch_bounds__(256) combine_kernel(float* __restrict__ out) {
    int n = blockIdx.x;
    int d = threadIdx.x * 4;
    float4 a = *(const float4*)&g_x1[(size_t)n * D_ + d];
    float4 b = *(const float4*)&g_contrib[(size_t)(n * 2 + 0) * D_ + d];
    float4 c = *(const float4*)&g_contrib[(size_t)(n * 2 + 1) * D_ + d];
    float4 r;
    r.x = a.x + b.x + c.x; r.y = a.y + b.y + c.y;
    r.z = a.z + b.z + c.z; r.w = a.w + b.w + c.w;
    *(float4*)&out[(size_t)n * D_ + d] = r;
}

// ---------------- host launcher ----------------
extern "C" void kernel_launch(void* const* d_in, const int* in_sizes, int n_in,
                              void* d_out, int out_size) {
    const float* x    = (const float*)d_in[0];
    const float* n1w  = (const float*)d_in[1];
    const float* wq   = (const float*)d_in[2];
    const float* bq   = (const float*)d_in[3];
    const float* wk   = (const float*)d_in[4];
    const float* bk   = (const float*)d_in[5];
    const float* wv   = (const float*)d_in[6];
    const float* bv   = (const float*)d_in[7];
    const float* woW  = (const float*)d_in[8];
    const float* bo   = (const float*)d_in[9];
    const float* sink = (const float*)d_in[10];
    const float* n2w  = (const float*)d_in[11];
    const float* rw   = (const float*)d_in[12];
    const float* rb   = (const float*)d_in[13];
    const float* w1   = (const float*)d_in[14];
    const float* b1   = (const float*)d_in[15];
    const float* w2   = (const float*)d_in[16];
    const float* b2   = (const float*)d_in[17];
    float* out = (float*)d_out;

    zero_kernel<<<1, 32>>>();
    rmsnorm1_kernel<<<S_, 256>>>(x, n1w);
    qkv_kernel<<<dim3(S_ / BM, 24), 128>>>(wq, bq, wk, bk, wv, bv);
    attn_kernel<<<S_, 256>>>(sink);
    wo_kernel<<<dim3(S_ / BM, D_ / BN), 128>>>(woW, bo, x);
    rmsnorm2_kernel<<<S_, 256>>>(n2w);
    router_kernel<<<S_, 128>>>(rw, rb);
    if (out_size > S_ * D_) {
        aux_kernel<<<1, 32>>>(out + (size_t)S_ * D_);
    }
    moe1_kernel<<<dim3(S_ / BM, HDIM_ / BN, E_), 128>>>(w1, b1);
    moe2_kernel<<<dim3(S_ / BM, D_ / BN, E_), 128>>>(w2, b2);
    combine_kernel<<<S_, 256>>>(out);
}